// round 3
// baseline (speedup 1.0000x reference)
#include <cuda_runtime.h>

// Holt double-exponential smoothing, ALPHA = BETA = 0.5.
// x: [B=32, N=2048, T=1024] float32, T contiguous. out same shape.
//   out[t=0] = 0
//   out[t=1] = x[1]
//   t>=2: scan from (s,b)=(0,0):
//     s' = 0.5*x_t + 0.5*(s+b);  b' = 0.5*(s'-s) + 0.5*b
// One thread per (b,n) sequence; float4 vectorized over T with one-ahead prefetch.

static constexpr int BATCH  = 32;
static constexpr int NEURON = 2048;
static constexpr int STEPS  = 1024;
static constexpr int NSEQ   = BATCH * NEURON;      // 65536
static constexpr int VEC    = STEPS / 4;           // 256 float4 per sequence
static constexpr int TPB    = 64;                  // small blocks -> smooth wave balance

__global__ __launch_bounds__(TPB)
void holt_smooth_kernel(const float* __restrict__ x, float* __restrict__ y) {
    const int seq = blockIdx.x * TPB + threadIdx.x;   // grid sized exactly
    const float4* __restrict__ xin  = reinterpret_cast<const float4*>(x) + (size_t)seq * VEC;
    float4*       __restrict__ yout = reinterpret_cast<float4*>(y)       + (size_t)seq * VEC;

    // Prologue: t = 0..3
    float4 v  = xin[0];
    float4 vn = xin[1];

    float4 r;
    r.x = 0.0f;        // t=0: zero init state
    r.y = v.y;         // t=1: s = x1 (state NOT carried forward)

    // t=2: recurrence from (s,b) = (0,0)
    float s = 0.5f * v.z;
    float b = 0.5f * s;
    r.z = s;

    // t=3
    {
        float sn = fmaf(0.5f, s + b, 0.5f * v.w);
        b = fmaf(0.5f, sn - s, 0.5f * b);
        s = sn;
        r.w = sn;
    }
    yout[0] = r;

    // Main loop: 255 float4 iterations, software-pipelined load
    #pragma unroll 5
    for (int i = 1; i < VEC; ++i) {
        v = vn;
        if (i + 1 < VEC) vn = xin[i + 1];

        float4 o;
        float sn;
        sn = fmaf(0.5f, s + b, 0.5f * v.x); b = fmaf(0.5f, sn - s, 0.5f * b); s = sn; o.x = sn;
        sn = fmaf(0.5f, s + b, 0.5f * v.y); b = fmaf(0.5f, sn - s, 0.5f * b); s = sn; o.y = sn;
        sn = fmaf(0.5f, s + b, 0.5f * v.z); b = fmaf(0.5f, sn - s, 0.5f * b); s = sn; o.z = sn;
        sn = fmaf(0.5f, s + b, 0.5f * v.w); b = fmaf(0.5f, sn - s, 0.5f * b); s = sn; o.w = sn;
        yout[i] = o;
    }
}

extern "C" void kernel_launch(void* const* d_in, const int* in_sizes, int n_in,
                              void* d_out, int out_size) {
    (void)in_sizes; (void)n_in; (void)out_size;
    const float* x = (const float*)d_in[0];
    float*       y = (float*)d_out;
    holt_smooth_kernel<<<NSEQ / TPB, TPB>>>(x, y);
}